// round 2
// baseline (speedup 1.0000x reference)
#include <cuda_runtime.h>
#include <cuda_bf16.h>
#include <math.h>

// ---------------------------------------------------------------------------
// Problem constants (shapes fixed by the dataset)
// ---------------------------------------------------------------------------
#define BB    64
#define CIN   64
#define COUT  64
#define HH    64
#define WW    64
#define NOUT  10
#define NFLAT (COUT * (HH/2) * (WW/2))   // 65536

// Output tuple packing (all float32, concatenated in reference return order):
// pooled_S [64,64,32,32], rreadout [64,10], argmax [64],
// P_new, Q_new, R_out, U  (each [64,64,64,64])
#define N_IMG   ((size_t)BB * COUT * HH * WW)          // 16,777,216
#define N_POOL  ((size_t)BB * COUT * (HH/2) * (WW/2))  // 4,194,304
#define OFF_PS  ((size_t)0)
#define OFF_RR  (OFF_PS + N_POOL)
#define OFF_AM  (OFF_RR + (size_t)BB * NOUT)
#define OFF_P   (OFF_AM + (size_t)BB)
#define OFF_Q   (OFF_P + N_IMG)
#define OFF_RO  (OFF_Q + N_IMG)
#define OFF_U   (OFF_RO + N_IMG)

// Scratch for U_aux = sigmoid(maxpool(U))  [64,64,32,32]
__device__ float g_uaux[N_POOL];

// ---------------------------------------------------------------------------
// Kernel 1: LIF state update (elementwise, float4 vectorized)
//   P_new = 0.95*P + 20*Q ; Q_new = 0.87*Q + 7.5*input
// ---------------------------------------------------------------------------
__global__ void lif_pq_kernel(const float* __restrict__ in_t,
                              const float* __restrict__ P,
                              const float* __restrict__ Q,
                              float* __restrict__ Pn,
                              float* __restrict__ Qn)
{
    size_t i = (size_t)blockIdx.x * blockDim.x + threadIdx.x;   // float4 index
    float4 p = ((const float4*)P)[i];
    float4 q = ((const float4*)Q)[i];
    float4 x = ((const float4*)in_t)[i];
    float4 pn, qn;
    pn.x = 0.95f*p.x + 20.0f*q.x;  pn.y = 0.95f*p.y + 20.0f*q.y;
    pn.z = 0.95f*p.z + 20.0f*q.z;  pn.w = 0.95f*p.w + 20.0f*q.w;
    qn.x = 0.87f*q.x + 7.5f*x.x;   qn.y = 0.87f*q.y + 7.5f*x.y;
    qn.z = 0.87f*q.z + 7.5f*x.z;   qn.w = 0.87f*q.w + 7.5f*x.w;
    ((float4*)Pn)[i] = pn;
    ((float4*)Qn)[i] = qn;
}

// ---------------------------------------------------------------------------
// Kernel 2: 3x3 conv (pad 1) + fused epilogue
//   U = conv(P_new, W) + 0.65*R
//   S = (U >= 1) ; R_out = 0.65*R - S
//   pooled_S = (max2x2(U) >= 1) ; U_aux = sigmoid(max2x2(U))
//
// CTA tile: 16 cout x 8 rows x 64 cols. Thread: 4 cout x 8 cols x 1 row.
//   t = xg (3b) | r (3b) | cog (2b)
// ci processed in chunks of 8 through shared memory.
// ---------------------------------------------------------------------------
__global__ __launch_bounds__(256)
void conv_fused_kernel(const float* __restrict__ Pn,
                       const float* __restrict__ R,
                       const float* __restrict__ Wt,
                       float* __restrict__ outU,
                       float* __restrict__ outRout,
                       float* __restrict__ outPS)
{
    __shared__ float s_in[8][10][68];   // [ci][row(-1..8)][col(-1..66 pad)]
    __shared__ float s_w[16][8][9];     // [co][ci][ky*3+kx]

    const int t   = threadIdx.x;
    const int y0  = blockIdx.x * 8;
    const int co0 = blockIdx.y * 16;
    const int b   = blockIdx.z;
    const int xg  = t & 7;
    const int r   = (t >> 3) & 7;
    const int cog = t >> 6;
    const int x0  = xg * 8;

    float acc[4][8];
    #pragma unroll
    for (int c = 0; c < 4; c++)
        #pragma unroll
        for (int xi = 0; xi < 8; xi++) acc[c][xi] = 0.0f;

    for (int ci0 = 0; ci0 < CIN; ci0 += 8) {
        __syncthreads();
        // weights chunk: 16co x 8ci x 9 = 1152 floats
        for (int idx = t; idx < 16*8*9; idx += 256) {
            int co  = idx / 72;
            int rem = idx - co * 72;
            s_w[co][rem / 9][rem % 9] = Wt[(size_t)(co0 + co) * 576 + (size_t)ci0 * 9 + rem];
        }
        // input tile: 8ci x 10rows x 68cols (halo + zero padding)
        for (int idx = t; idx < 8*10*68; idx += 256) {
            int ci  = idx / 680;
            int rem = idx - ci * 680;
            int row = rem / 68;
            int col = rem - row * 68;
            int gy  = y0 - 1 + row;
            int gx  = col - 1;
            float v = 0.0f;
            if (col < 66 && (unsigned)gy < (unsigned)HH && (unsigned)gx < (unsigned)WW)
                v = Pn[(((size_t)b * CIN + ci0 + ci) * HH + gy) * WW + gx];
            s_in[ci][row][col] = v;
        }
        __syncthreads();

        #pragma unroll
        for (int ci = 0; ci < 8; ci++) {
            // hoist this ci's weights for our 4 cout into registers (36 LDS)
            float wreg[4][9];
            #pragma unroll
            for (int c = 0; c < 4; c++)
                #pragma unroll
                for (int k = 0; k < 9; k++)
                    wreg[c][k] = s_w[cog * 4 + c][ci][k];

            #pragma unroll
            for (int ky = 0; ky < 3; ky++) {
                const float* rp = &s_in[ci][r + ky][x0];
                float4 a  = *(const float4*)(rp);
                float4 bb = *(const float4*)(rp + 4);
                float2 cc = *(const float2*)(rp + 8);
                float rin[10] = {a.x, a.y, a.z, a.w, bb.x, bb.y, bb.z, bb.w, cc.x, cc.y};
                #pragma unroll
                for (int kx = 0; kx < 3; kx++) {
                    #pragma unroll
                    for (int c = 0; c < 4; c++) {
                        float w = wreg[c][ky * 3 + kx];
                        #pragma unroll
                        for (int xi = 0; xi < 8; xi++)
                            acc[c][xi] = fmaf(rin[kx + xi], w, acc[c][xi]);
                    }
                }
            }
        }
    }

    // -------- fused epilogue --------
    const int y = y0 + r;
    #pragma unroll
    for (int c = 0; c < 4; c++) {
        int co = co0 + cog * 4 + c;
        size_t base = (((size_t)b * COUT + co) * HH + y) * WW + x0;
        float4 r0 = *(const float4*)(R + base);
        float4 r1 = *(const float4*)(R + base + 4);
        float rv[8] = {r0.x, r0.y, r0.z, r0.w, r1.x, r1.y, r1.z, r1.w};

        float u[8], ro[8];
        #pragma unroll
        for (int xi = 0; xi < 8; xi++) {
            float rn = 0.65f * rv[xi];
            u[xi]  = acc[c][xi] + rn;
            float s = (u[xi] >= 1.0f) ? 1.0f : 0.0f;
            ro[xi] = rn - s;
        }
        float4 uo0 = make_float4(u[0], u[1], u[2], u[3]);
        float4 uo1 = make_float4(u[4], u[5], u[6], u[7]);
        float4 ro0 = make_float4(ro[0], ro[1], ro[2], ro[3]);
        float4 ro1 = make_float4(ro[4], ro[5], ro[6], ro[7]);
        *(float4*)(outU + base)        = uo0;
        *(float4*)(outU + base + 4)    = uo1;
        *(float4*)(outRout + base)     = ro0;
        *(float4*)(outRout + base + 4) = ro1;

        // horizontal max over x-pairs
        float m0 = fmaxf(u[0], u[1]);
        float m1 = fmaxf(u[2], u[3]);
        float m2 = fmaxf(u[4], u[5]);
        float m3 = fmaxf(u[6], u[7]);
        // vertical exchange with row partner (t ^ 8 flips r bit0, same warp)
        float p0 = fmaxf(m0, __shfl_xor_sync(0xffffffffu, m0, 8));
        float p1 = fmaxf(m1, __shfl_xor_sync(0xffffffffu, m1, 8));
        float p2 = fmaxf(m2, __shfl_xor_sync(0xffffffffu, m2, 8));
        float p3 = fmaxf(m3, __shfl_xor_sync(0xffffffffu, m3, 8));

        if ((r & 1) == 0) {
            int py  = y >> 1;
            int px0 = x0 >> 1;
            size_t pb = (((size_t)b * COUT + co) * (HH/2) + py) * (WW/2) + px0;
            float4 ps = make_float4(p0 >= 1.0f ? 1.0f : 0.0f,
                                    p1 >= 1.0f ? 1.0f : 0.0f,
                                    p2 >= 1.0f ? 1.0f : 0.0f,
                                    p3 >= 1.0f ? 1.0f : 0.0f);
            float4 ua = make_float4(1.0f / (1.0f + expf(-p0)),
                                    1.0f / (1.0f + expf(-p1)),
                                    1.0f / (1.0f + expf(-p2)),
                                    1.0f / (1.0f + expf(-p3)));
            *(float4*)(outPS + pb)  = ps;
            *(float4*)(g_uaux + pb) = ua;
        }
    }
}

// ---------------------------------------------------------------------------
// Kernel 3: readout GEMV + argmax.  One CTA per batch element.
//   rreadout[b,o] = sum_f U_aux[b,f] * readout_w[o,f]
// ---------------------------------------------------------------------------
__global__ __launch_bounds__(512)
void readout_kernel(const float* __restrict__ rw,
                    float* __restrict__ outRR,
                    float* __restrict__ outAM)
{
    const int b = blockIdx.x;
    const int t = threadIdx.x;
    const float* ub = g_uaux + (size_t)b * NFLAT;

    float acc[NOUT];
    #pragma unroll
    for (int o = 0; o < NOUT; o++) acc[o] = 0.0f;

    for (int f = t * 4; f < NFLAT; f += 512 * 4) {
        float4 u4 = *(const float4*)(ub + f);
        #pragma unroll
        for (int o = 0; o < NOUT; o++) {
            float4 w4 = *(const float4*)(rw + (size_t)o * NFLAT + f);
            acc[o] += u4.x * w4.x + u4.y * w4.y + u4.z * w4.z + u4.w * w4.w;
        }
    }

    // warp reduce
    #pragma unroll
    for (int o = 0; o < NOUT; o++)
        #pragma unroll
        for (int s = 16; s > 0; s >>= 1)
            acc[o] += __shfl_xor_sync(0xffffffffu, acc[o], s);

    __shared__ float sp[NOUT][16];
    __shared__ float fin[NOUT];
    int warp = t >> 5, lane = t & 31;
    if (lane == 0) {
        #pragma unroll
        for (int o = 0; o < NOUT; o++) sp[o][warp] = acc[o];
    }
    __syncthreads();
    if (t < NOUT) {
        float v = 0.0f;
        #pragma unroll
        for (int w = 0; w < 16; w++) v += sp[t][w];
        outRR[(size_t)b * NOUT + t] = v;
        fin[t] = v;
    }
    __syncthreads();
    if (t == 0) {
        int   bi = 0;
        float bv = fin[0];
        #pragma unroll
        for (int o = 1; o < NOUT; o++)
            if (fin[o] > bv) { bv = fin[o]; bi = o; }   // first-max: strict >
        outAM[b] = (float)bi;
    }
}

// ---------------------------------------------------------------------------
// Launch
// ---------------------------------------------------------------------------
extern "C" void kernel_launch(void* const* d_in, const int* in_sizes, int n_in,
                              void* d_out, int out_size)
{
    const float* in_t = (const float*)d_in[0];
    const float* P    = (const float*)d_in[1];
    const float* Q    = (const float*)d_in[2];
    const float* R    = (const float*)d_in[3];
    const float* Wt   = (const float*)d_in[4];
    const float* rw   = (const float*)d_in[5];
    // d_in[6] = y_local (unused by the returned outputs)

    float* out    = (float*)d_out;
    float* outPS  = out + OFF_PS;
    float* outRR  = out + OFF_RR;
    float* outAM  = out + OFF_AM;
    float* outP   = out + OFF_P;
    float* outQ   = out + OFF_Q;
    float* outRO  = out + OFF_RO;
    float* outU   = out + OFF_U;

    // 1) LIF state update: writes P_new/Q_new into the output buffer;
    //    conv reads P_new back from there (no scratch needed).
    lif_pq_kernel<<<(int)(N_IMG / 4 / 256), 256>>>(in_t, P, Q, outP, outQ);

    // 2) Conv + U/S/R_out + pooling epilogue
    dim3 gconv(HH / 8, COUT / 16, BB);
    conv_fused_kernel<<<gconv, 256>>>(outP, R, Wt, outU, outRO, outPS);

    // 3) Readout GEMV + argmax
    readout_kernel<<<BB, 512>>>(rw, outRR, outAM);
}

// round 3
// speedup vs baseline: 1.0063x; 1.0063x over previous
#include <cuda_runtime.h>
#include <cuda_bf16.h>
#include <math.h>

// ---------------------------------------------------------------------------
// Problem constants (shapes fixed by the dataset)
// ---------------------------------------------------------------------------
#define BB    64
#define CIN   64
#define COUT  64
#define HH    64
#define WW    64
#define NOUT  10
#define NFLAT (COUT * (HH/2) * (WW/2))   // 65536

// Output tuple packing (all float32, concatenated in reference return order):
// pooled_S [64,64,32,32], rreadout [64,10], argmax [64],
// P_new, Q_new, R_out, U  (each [64,64,64,64])
#define N_IMG   ((size_t)BB * COUT * HH * WW)          // 16,777,216
#define N_POOL  ((size_t)BB * COUT * (HH/2) * (WW/2))  // 4,194,304
#define OFF_PS  ((size_t)0)
#define OFF_RR  (OFF_PS + N_POOL)
#define OFF_AM  (OFF_RR + (size_t)BB * NOUT)
#define OFF_P   (OFF_AM + (size_t)BB)
#define OFF_Q   (OFF_P + N_IMG)
#define OFF_RO  (OFF_Q + N_IMG)
#define OFF_U   (OFF_RO + N_IMG)

// Scratch for U_aux = sigmoid(maxpool(U))  [64,64,32,32]
__device__ float g_uaux[N_POOL];

// ---------------------------------------------------------------------------
// Kernel 1: LIF state update (elementwise, float4 vectorized)
//   P_new = 0.95*P + 20*Q ; Q_new = 0.87*Q + 7.5*input
// ---------------------------------------------------------------------------
__global__ void lif_pq_kernel(const float* __restrict__ in_t,
                              const float* __restrict__ P,
                              const float* __restrict__ Q,
                              float* __restrict__ Pn,
                              float* __restrict__ Qn)
{
    size_t i = (size_t)blockIdx.x * blockDim.x + threadIdx.x;   // float4 index
    float4 p = ((const float4*)P)[i];
    float4 q = ((const float4*)Q)[i];
    float4 x = ((const float4*)in_t)[i];
    float4 pn, qn;
    pn.x = 0.95f*p.x + 20.0f*q.x;  pn.y = 0.95f*p.y + 20.0f*q.y;
    pn.z = 0.95f*p.z + 20.0f*q.z;  pn.w = 0.95f*p.w + 20.0f*q.w;
    qn.x = 0.87f*q.x + 7.5f*x.x;   qn.y = 0.87f*q.y + 7.5f*x.y;
    qn.z = 0.87f*q.z + 7.5f*x.z;   qn.w = 0.87f*q.w + 7.5f*x.w;
    ((float4*)Pn)[i] = pn;
    ((float4*)Qn)[i] = qn;
}

// ---------------------------------------------------------------------------
// Kernel 2: 3x3 conv (pad 1) + fused epilogue
//   U = conv(P_new, W) + 0.65*R
//   S = (U >= 1) ; R_out = 0.65*R - S
//   pooled_S = (max2x2(U) >= 1) ; U_aux = sigmoid(max2x2(U))
//
// CTA tile: 16 cout x 8 rows x 64 cols. Thread: 4 cout x 8 cols x 1 row.
//   t = xg (3b) | r (3b) | cog (2b)
// ci processed in chunks of 8 through shared memory.
// ---------------------------------------------------------------------------
__global__ __launch_bounds__(256)
void conv_fused_kernel(const float* __restrict__ Pn,
                       const float* __restrict__ R,
                       const float* __restrict__ Wt,
                       float* __restrict__ outU,
                       float* __restrict__ outRout,
                       float* __restrict__ outPS)
{
    __shared__ float s_in[8][10][68];   // [ci][row(-1..8)][col(-1..66 pad)]
    __shared__ float s_w[16][8][9];     // [co][ci][ky*3+kx]

    const int t   = threadIdx.x;
    const int y0  = blockIdx.x * 8;
    const int co0 = blockIdx.y * 16;
    const int b   = blockIdx.z;
    const int xg  = t & 7;
    const int r   = (t >> 3) & 7;
    const int cog = t >> 6;
    const int x0  = xg * 8;

    float acc[4][8];
    #pragma unroll
    for (int c = 0; c < 4; c++)
        #pragma unroll
        for (int xi = 0; xi < 8; xi++) acc[c][xi] = 0.0f;

    for (int ci0 = 0; ci0 < CIN; ci0 += 8) {
        __syncthreads();
        // weights chunk: 16co x 8ci x 9 = 1152 floats
        for (int idx = t; idx < 16*8*9; idx += 256) {
            int co  = idx / 72;
            int rem = idx - co * 72;
            s_w[co][rem / 9][rem % 9] = Wt[(size_t)(co0 + co) * 576 + (size_t)ci0 * 9 + rem];
        }
        // input tile: 8ci x 10rows x 68cols (halo + zero padding)
        for (int idx = t; idx < 8*10*68; idx += 256) {
            int ci  = idx / 680;
            int rem = idx - ci * 680;
            int row = rem / 68;
            int col = rem - row * 68;
            int gy  = y0 - 1 + row;
            int gx  = col - 1;
            float v = 0.0f;
            if (col < 66 && (unsigned)gy < (unsigned)HH && (unsigned)gx < (unsigned)WW)
                v = Pn[(((size_t)b * CIN + ci0 + ci) * HH + gy) * WW + gx];
            s_in[ci][row][col] = v;
        }
        __syncthreads();

        #pragma unroll
        for (int ci = 0; ci < 8; ci++) {
            // hoist this ci's weights for our 4 cout into registers (36 LDS)
            float wreg[4][9];
            #pragma unroll
            for (int c = 0; c < 4; c++)
                #pragma unroll
                for (int k = 0; k < 9; k++)
                    wreg[c][k] = s_w[cog * 4 + c][ci][k];

            #pragma unroll
            for (int ky = 0; ky < 3; ky++) {
                const float* rp = &s_in[ci][r + ky][x0];
                float4 a  = *(const float4*)(rp);
                float4 bb = *(const float4*)(rp + 4);
                float2 cc = *(const float2*)(rp + 8);
                float rin[10] = {a.x, a.y, a.z, a.w, bb.x, bb.y, bb.z, bb.w, cc.x, cc.y};
                #pragma unroll
                for (int kx = 0; kx < 3; kx++) {
                    #pragma unroll
                    for (int c = 0; c < 4; c++) {
                        float w = wreg[c][ky * 3 + kx];
                        #pragma unroll
                        for (int xi = 0; xi < 8; xi++)
                            acc[c][xi] = fmaf(rin[kx + xi], w, acc[c][xi]);
                    }
                }
            }
        }
    }

    // -------- fused epilogue --------
    const int y = y0 + r;
    #pragma unroll
    for (int c = 0; c < 4; c++) {
        int co = co0 + cog * 4 + c;
        size_t base = (((size_t)b * COUT + co) * HH + y) * WW + x0;
        float4 r0 = *(const float4*)(R + base);
        float4 r1 = *(const float4*)(R + base + 4);
        float rv[8] = {r0.x, r0.y, r0.z, r0.w, r1.x, r1.y, r1.z, r1.w};

        float u[8], ro[8];
        #pragma unroll
        for (int xi = 0; xi < 8; xi++) {
            float rn = 0.65f * rv[xi];
            u[xi]  = acc[c][xi] + rn;
            float s = (u[xi] >= 1.0f) ? 1.0f : 0.0f;
            ro[xi] = rn - s;
        }
        float4 uo0 = make_float4(u[0], u[1], u[2], u[3]);
        float4 uo1 = make_float4(u[4], u[5], u[6], u[7]);
        float4 ro0 = make_float4(ro[0], ro[1], ro[2], ro[3]);
        float4 ro1 = make_float4(ro[4], ro[5], ro[6], ro[7]);
        *(float4*)(outU + base)        = uo0;
        *(float4*)(outU + base + 4)    = uo1;
        *(float4*)(outRout + base)     = ro0;
        *(float4*)(outRout + base + 4) = ro1;

        // horizontal max over x-pairs
        float m0 = fmaxf(u[0], u[1]);
        float m1 = fmaxf(u[2], u[3]);
        float m2 = fmaxf(u[4], u[5]);
        float m3 = fmaxf(u[6], u[7]);
        // vertical exchange with row partner (t ^ 8 flips r bit0, same warp)
        float p0 = fmaxf(m0, __shfl_xor_sync(0xffffffffu, m0, 8));
        float p1 = fmaxf(m1, __shfl_xor_sync(0xffffffffu, m1, 8));
        float p2 = fmaxf(m2, __shfl_xor_sync(0xffffffffu, m2, 8));
        float p3 = fmaxf(m3, __shfl_xor_sync(0xffffffffu, m3, 8));

        if ((r & 1) == 0) {
            int py  = y >> 1;
            int px0 = x0 >> 1;
            size_t pb = (((size_t)b * COUT + co) * (HH/2) + py) * (WW/2) + px0;
            float4 ps = make_float4(p0 >= 1.0f ? 1.0f : 0.0f,
                                    p1 >= 1.0f ? 1.0f : 0.0f,
                                    p2 >= 1.0f ? 1.0f : 0.0f,
                                    p3 >= 1.0f ? 1.0f : 0.0f);
            float4 ua = make_float4(1.0f / (1.0f + expf(-p0)),
                                    1.0f / (1.0f + expf(-p1)),
                                    1.0f / (1.0f + expf(-p2)),
                                    1.0f / (1.0f + expf(-p3)));
            *(float4*)(outPS + pb)  = ps;
            *(float4*)(g_uaux + pb) = ua;
        }
    }
}

// ---------------------------------------------------------------------------
// Kernel 3: readout GEMV + argmax.  One CTA per batch element.
//   rreadout[b,o] = sum_f U_aux[b,f] * readout_w[o,f]
// ---------------------------------------------------------------------------
__global__ __launch_bounds__(512)
void readout_kernel(const float* __restrict__ rw,
                    float* __restrict__ outRR,
                    float* __restrict__ outAM)
{
    const int b = blockIdx.x;
    const int t = threadIdx.x;
    const float* ub = g_uaux + (size_t)b * NFLAT;

    float acc[NOUT];
    #pragma unroll
    for (int o = 0; o < NOUT; o++) acc[o] = 0.0f;

    for (int f = t * 4; f < NFLAT; f += 512 * 4) {
        float4 u4 = *(const float4*)(ub + f);
        #pragma unroll
        for (int o = 0; o < NOUT; o++) {
            float4 w4 = *(const float4*)(rw + (size_t)o * NFLAT + f);
            acc[o] += u4.x * w4.x + u4.y * w4.y + u4.z * w4.z + u4.w * w4.w;
        }
    }

    // warp reduce
    #pragma unroll
    for (int o = 0; o < NOUT; o++)
        #pragma unroll
        for (int s = 16; s > 0; s >>= 1)
            acc[o] += __shfl_xor_sync(0xffffffffu, acc[o], s);

    __shared__ float sp[NOUT][16];
    __shared__ float fin[NOUT];
    int warp = t >> 5, lane = t & 31;
    if (lane == 0) {
        #pragma unroll
        for (int o = 0; o < NOUT; o++) sp[o][warp] = acc[o];
    }
    __syncthreads();
    if (t < NOUT) {
        float v = 0.0f;
        #pragma unroll
        for (int w = 0; w < 16; w++) v += sp[t][w];
        outRR[(size_t)b * NOUT + t] = v;
        fin[t] = v;
    }
    __syncthreads();
    if (t == 0) {
        int   bi = 0;
        float bv = fin[0];
        #pragma unroll
        for (int o = 1; o < NOUT; o++)
            if (fin[o] > bv) { bv = fin[o]; bi = o; }   // first-max: strict >
        outAM[b] = (float)bi;
    }
}

// ---------------------------------------------------------------------------
// Launch
// ---------------------------------------------------------------------------
extern "C" void kernel_launch(void* const* d_in, const int* in_sizes, int n_in,
                              void* d_out, int out_size)
{
    const float* in_t = (const float*)d_in[0];
    const float* P    = (const float*)d_in[1];
    const float* Q    = (const float*)d_in[2];
    const float* R    = (const float*)d_in[3];
    const float* Wt   = (const float*)d_in[4];
    const float* rw   = (const float*)d_in[5];
    // d_in[6] = y_local (unused by the returned outputs)

    float* out    = (float*)d_out;
    float* outPS  = out + OFF_PS;
    float* outRR  = out + OFF_RR;
    float* outAM  = out + OFF_AM;
    float* outP   = out + OFF_P;
    float* outQ   = out + OFF_Q;
    float* outRO  = out + OFF_RO;
    float* outU   = out + OFF_U;

    // 1) LIF state update: writes P_new/Q_new into the output buffer;
    //    conv reads P_new back from there (no scratch needed).
    lif_pq_kernel<<<(int)(N_IMG / 4 / 256), 256>>>(in_t, P, Q, outP, outQ);

    // 2) Conv + U/S/R_out + pooling epilogue
    dim3 gconv(HH / 8, COUT / 16, BB);
    conv_fused_kernel<<<gconv, 256>>>(outP, R, Wt, outU, outRO, outPS);

    // 3) Readout GEMV + argmax
    readout_kernel<<<BB, 512>>>(rw, outRR, outAM);
}